// round 8
// baseline (speedup 1.0000x reference)
#include <cuda_runtime.h>

#define CIN   384
#define FEAT  192
#define CGATE 768
#define NB    16
#define NH    64
#define NW    64
#define NBLK  128     // persistent blocks: 16 batch-tiles x 8 gate-col tiles

#define SLAB_STRIDE 72
// dynamic smem layout (floats):
//   slab : 192*72            = 13824   (h_{y-1}[f][w] with halo, data at j=w+1)
//   Bs   : 2*32*96           =  6144   (double-buffered weight k-chunks)
//   Ss   : 96*68             =  6528   (s tile for gate re-mapping)
//   Cs   : 24*64             =  1536   (cell state, persistent across rows)
#define SMEM_FLOATS (13824 + 6144 + 6528 + 1536)
#define SMEM_BYTES  (SMEM_FLOATS * 4)

// ---------------- device scratch ----------------
__device__ float g_hpre[(size_t)NH * NB * NW * CGATE];  // [m][n'] n' = f*4 + gate
__device__ float g_outh[(size_t)NH * NB * FEAT * NW];   // [y][b][f][w]
__device__ float g_wA[CIN * 2 * CGATE];                 // i2s masked+shuffled, cols n'=f*4+q
__device__ float g_wR[FEAT * 3 * CGATE];                // s2s, rows k=kw*192+ci, cols n'=f*4+q
__device__ float g_wS[FEAT * CIN];                      // skip masked, [f][cin]
__device__ int   g_sync;                                // inter-block barrier counter

// ---------------- weight prep ----------------
__global__ void prep_weights(const float* __restrict__ w_i2s,
                             const float* __restrict__ w_s2s,
                             const float* __restrict__ w_skip) {
    int stride = gridDim.x * blockDim.x;
    int t0 = blockIdx.x * blockDim.x + threadIdx.x;
    if (t0 == 0) g_sync = 0;                       // reset barrier each launch

    // g_wA: [k=ci*2+tap][n'=f*4+q]; shuffled source channel cg = g*256 + q*64 + r
    for (int i = t0; i < CIN * 2 * CGATE; i += stride) {
        int k = i / CGATE, np = i % CGATE;
        int ci = k >> 1, tap = k & 1;
        int q = np & 3, f = np >> 2;
        int g = f >> 6, r = f & 63;
        int cg = g * 256 + q * 64 + r;
        float v = w_i2s[(cg * CIN + ci) * 3 + tap];
        if (tap == 1 && g < (ci >> 7)) v = 0.f;    // center tap mask; right tap dropped
        g_wA[i] = v;
    }
    // g_wR: [k=kw*192+ci][n'=f*4+q]
    for (int i = t0; i < FEAT * 3 * CGATE; i += stride) {
        int k = i / CGATE, np = i % CGATE;
        int kw = k / 192, ci = k - kw * 192;
        int q = np & 3, f = np >> 2;
        g_wR[i] = w_s2s[((q * 192 + f) * FEAT + ci) * 3 + kw];
    }
    // g_wS: masked 1x1 skip, transposed to [f][cin]
    for (int i = t0; i < FEAT * CIN; i += stride) {
        int f = i / CIN, c = i % CIN;
        g_wS[i] = ((c >> 7) >= (f >> 6)) ? w_skip[c * FEAT + f] : 0.f;
    }
}

// ---------------- phase 1: input conv GEMM ----------------
__global__ __launch_bounds__(256, 2) void phase1_gemm(const float* __restrict__ x) {
    __shared__ float As[16][128];
    __shared__ float Bs[16][64];
    const int m0 = blockIdx.x * 128;
    const int n0 = blockIdx.y * 64;
    const int tid = threadIdx.x;
    const int tx = tid & 15;   // n
    const int ty = tid >> 4;   // m

    float acc[8][4];
#pragma unroll
    for (int i = 0; i < 8; i++)
#pragma unroll
        for (int j = 0; j < 4; j++) acc[i][j] = 0.f;

    for (int k0 = 0; k0 < CIN * 2; k0 += 16) {
#pragma unroll
        for (int i = 0; i < 8; i++) {
            int idx = tid + i * 256;
            int kk = idx >> 7, mm = idx & 127;
            int m = m0 + mm;
            int w = m & 63, b = (m >> 6) & 15, y = m >> 10;
            int kg = k0 + kk;
            int ci = kg >> 1, tap = kg & 1;
            int xw = w + tap - 1;
            float v = 0.f;
            if (xw >= 0) v = x[((b * CIN + ci) * NH + y) * NW + xw];
            As[kk][mm] = v;
        }
#pragma unroll
        for (int i = 0; i < 4; i++) {
            int idx = tid + i * 256;
            int kk = idx >> 6, nn = idx & 63;
            Bs[kk][nn] = g_wA[(k0 + kk) * CGATE + n0 + nn];
        }
        __syncthreads();
#pragma unroll
        for (int k = 0; k < 16; k++) {
            float4 a0 = *(const float4*)&As[k][ty * 8];
            float4 a1 = *(const float4*)&As[k][ty * 8 + 4];
            float4 bv = *(const float4*)&Bs[k][tx * 4];
            float a[8] = {a0.x, a0.y, a0.z, a0.w, a1.x, a1.y, a1.z, a1.w};
            float bb[4] = {bv.x, bv.y, bv.z, bv.w};
#pragma unroll
            for (int i = 0; i < 8; i++)
#pragma unroll
                for (int j = 0; j < 4; j++)
                    acc[i][j] = fmaf(a[i], bb[j], acc[i][j]);
        }
        __syncthreads();
    }
#pragma unroll
    for (int i = 0; i < 8; i++) {
        int m = m0 + ty * 8 + i;
        float4 v = make_float4(acc[i][0], acc[i][1], acc[i][2], acc[i][3]);
        *(float4*)&g_hpre[(size_t)m * CGATE + n0 + tx * 4] = v;
    }
}

// ---------------- phase 2: persistent fused recurrence ----------------
__device__ __forceinline__ float sigm(float v) { return 1.f / (1.f + __expf(-v)); }

__global__ __launch_bounds__(256, 1) void recurrence() {
    extern __shared__ float sm[];
    float* slab = sm;                       // 192 x 72
    float* Bsm  = sm + 13824;               // 2 x 32 x 96
    float* Ss   = sm + 13824 + 6144;        // 96 x 68
    float* Cs   = Ss + 6528;                // 24 x 64

    const int tid = threadIdx.x;
    const int tx = tid & 15;                // m-lane: owns m = tx + 16*i
    const int ty = tid >> 4;                // n-lane: owns n' = ty*6 .. +5
    const int bm = blockIdx.x & 15;         // batch b
    const int bn = blockIdx.x >> 4;         // 0..7, n0 = bn*96, f0 = bn*24
    const int n0 = bn * 96;

    // one-time init (first use is after a __syncthreads)
    for (int p = tid; p < 1536; p += 256) Cs[p] = 0.f;
    if (tid < 192) { slab[tid * SLAB_STRIDE] = 0.f; slab[tid * SLAB_STRIDE + 65] = 0.f; }

    for (int y = 0; y < NH; y++) {
        // prefetch hpre tile into regs (consumed at epilogue -> latency hidden by GEMM)
        float pre[6][4];
        {
            size_t mb = (size_t)(y * NB + bm) * NW;
#pragma unroll
            for (int i = 0; i < 4; i++) {
                const float* p = &g_hpre[(mb + tx + i * 16) * CGATE + n0 + ty * 6];
                float2 v0 = *(const float2*)(p);
                float2 v1 = *(const float2*)(p + 2);
                float2 v2 = *(const float2*)(p + 4);
                pre[0][i] = v0.x; pre[1][i] = v0.y;
                pre[2][i] = v1.x; pre[3][i] = v1.y;
                pre[4][i] = v2.x; pre[5][i] = v2.y;
            }
        }

        float acc[6][4];
#pragma unroll
        for (int j = 0; j < 6; j++)
#pragma unroll
            for (int i = 0; i < 4; i++) acc[j][i] = 0.f;

        if (y > 0) {
            // load previous-row h slab [192][64] into smem (data at j = w+1; halos zero)
            const float* hp = &g_outh[(size_t)((y - 1) * NB + bm) * FEAT * NW];
#pragma unroll
            for (int r = 0; r < 12; r++) {
                int lin = tid + r * 256;            // float4 index 0..3071
                int f = lin >> 4;
                int w4 = (lin & 15) << 2;
                float4 v = *(const float4*)&hp[f * NW + w4];
                float* d = &slab[f * SLAB_STRIDE + 1 + w4];
                d[0] = v.x; d[1] = v.y; d[2] = v.z; d[3] = v.w;
            }
            // preload weight chunk 0
            float4 bfr[3];
#pragma unroll
            for (int r = 0; r < 3; r++) {
                int lin = tid + r * 256;            // 0..767 float4
                int kk = lin / 24;
                int nn = (lin % 24) << 2;
                bfr[r] = *(const float4*)&g_wR[(size_t)kk * CGATE + n0 + nn];
            }
#pragma unroll
            for (int r = 0; r < 3; r++) {
                int lin = tid + r * 256;
                int kk = lin / 24;
                int nn = (lin % 24) << 2;
                *(float4*)&Bsm[kk * 96 + nn] = bfr[r];
            }
            __syncthreads();

            for (int kc = 0; kc < 18; kc++) {
                if (kc + 1 < 18) {                  // prefetch next weight chunk (gmem, long latency)
#pragma unroll
                    for (int r = 0; r < 3; r++) {
                        int lin = tid + r * 256;
                        int kk = lin / 24;
                        int nn = (lin % 24) << 2;
                        bfr[r] = *(const float4*)&g_wR[(size_t)((kc + 1) * 32 + kk) * CGATE + n0 + nn];
                    }
                }
                // k = kw*192 + ci ordering: kw uniform per chunk -> A addr is base + kk*72
                int kw  = kc / 6;
                int ci0 = (kc - kw * 6) * 32;
                const float* aP = &slab[ci0 * SLAB_STRIDE + tx + kw];
                const float* bP = &Bsm[(kc & 1) * 3072 + ty * 6];

                // ---- software-pipelined inner loop: LDS(kk+1) issues before FMA(kk) ----
                float ar[2][4], br[2][6];
                {
                    ar[0][0] = aP[0];  ar[0][1] = aP[16]; ar[0][2] = aP[32]; ar[0][3] = aP[48];
                    float2 t0 = *(const float2*)&bP[0];
                    float2 t1 = *(const float2*)&bP[2];
                    float2 t2 = *(const float2*)&bP[4];
                    br[0][0] = t0.x; br[0][1] = t0.y; br[0][2] = t1.x;
                    br[0][3] = t1.y; br[0][4] = t2.x; br[0][5] = t2.y;
                }
#pragma unroll
                for (int kk = 0; kk < 32; kk++) {
                    const int cur = kk & 1, nxt = cur ^ 1;
                    if (kk < 31) {
                        const float* ap = aP + (kk + 1) * SLAB_STRIDE;
                        ar[nxt][0] = ap[0];  ar[nxt][1] = ap[16];
                        ar[nxt][2] = ap[32]; ar[nxt][3] = ap[48];
                        const float* bp = bP + (kk + 1) * 96;
                        float2 t0 = *(const float2*)&bp[0];
                        float2 t1 = *(const float2*)&bp[2];
                        float2 t2 = *(const float2*)&bp[4];
                        br[nxt][0] = t0.x; br[nxt][1] = t0.y; br[nxt][2] = t1.x;
                        br[nxt][3] = t1.y; br[nxt][4] = t2.x; br[nxt][5] = t2.y;
                    }
#pragma unroll
                    for (int j = 0; j < 6; j++)
#pragma unroll
                        for (int i = 0; i < 4; i++)
                            acc[j][i] = fmaf(ar[cur][i], br[cur][j], acc[j][i]);
                }

                if (kc + 1 < 18) {                  // commit next chunk to other buffer
                    float* bD = &Bsm[((kc + 1) & 1) * 3072];
#pragma unroll
                    for (int r = 0; r < 3; r++) {
                        int lin = tid + r * 256;
                        int kk = lin / 24;
                        int nn = (lin % 24) << 2;
                        *(float4*)&bD[kk * 96 + nn] = bfr[r];
                    }
                }
                __syncthreads();
            }
        } else {
            __syncthreads();   // cover Cs/halo init before first epilogue use
        }

        // epilogue: s = acc + hpre -> Ss (re-map so one thread sees all 4 gates of an f)
#pragma unroll
        for (int j = 0; j < 6; j++) {
            float* d = &Ss[(ty * 6 + j) * 68 + tx];
            d[0]  = acc[j][0] + pre[j][0];
            d[16] = acc[j][1] + pre[j][1];
            d[32] = acc[j][2] + pre[j][2];
            d[48] = acc[j][3] + pre[j][3];
        }
        __syncthreads();

        // fused LSTM gates + cell update + h writeback
        float* outp = &g_outh[(size_t)((y * NB + bm) * FEAT + bn * 24) * NW];
#pragma unroll
        for (int r = 0; r < 6; r++) {
            int p = tid + r * 256;                  // 0..1535 = f_local*64 + w
            int fl = p >> 6;
            int w = p & 63;
            float so = sigm(Ss[(fl * 4 + 0) * 68 + w]);
            float sf = sigm(Ss[(fl * 4 + 1) * 68 + w]);
            float si = sigm(Ss[(fl * 4 + 2) * 68 + w]);
            float sg = sigm(Ss[(fl * 4 + 3) * 68 + w]);
            float c = fmaf(sf, Cs[p], si * sg);
            Cs[p] = c;
            outp[fl * NW + w] = so * tanhf(c);
        }

        // inter-block barrier (also orders Ss consumption vs next row's writes):
        // syncthreads -> tid0 release-add -> tid0 acquire-spin -> syncthreads.
        // CTA barrier + scoped release/acquire gives cumulative visibility of all
        // threads' g_outh stores to all other blocks (same pattern as CG grid.sync).
        if (y < NH - 1) {
            __syncthreads();
            if (tid == 0) {
                int* sp = &g_sync;
                asm volatile("red.release.gpu.global.add.s32 [%0], 1;" :: "l"(sp) : "memory");
                int target = NBLK * (y + 1);
                int v;
                do {
                    asm volatile("ld.acquire.gpu.global.s32 %0, [%1];" : "=r"(v) : "l"(sp) : "memory");
                } while (v < target);
            }
            __syncthreads();
        } else {
            __syncthreads();                        // protect Ss on the final row (paranoia; cheap)
        }
    }
}

// ---------------- phase 3: skip conv GEMM + residual ----------------
__global__ __launch_bounds__(256, 2) void phase3_gemm(const float* __restrict__ x,
                                                      const float* __restrict__ b_skip,
                                                      float* __restrict__ out) {
    __shared__ float As[16][128];
    __shared__ float Bs[16][64];
    const int m0 = blockIdx.x * 128;    // m = (b*64+y)*64 + w
    const int n0 = blockIdx.y * 64;     // n = cin
    const int tid = threadIdx.x;
    const int tx = tid & 15;   // m dir
    const int ty = tid >> 4;   // n dir

    float acc[2][4][4];
#pragma unroll
    for (int h = 0; h < 2; h++)
#pragma unroll
        for (int i = 0; i < 4; i++)
#pragma unroll
            for (int j = 0; j < 4; j++) acc[h][i][j] = 0.f;

    for (int k0 = 0; k0 < FEAT; k0 += 16) {
#pragma unroll
        for (int i = 0; i < 8; i++) {
            int idx = tid + i * 256;
            int kk = idx >> 7, mm = idx & 127;
            int m = m0 + mm;
            int w = m & 63, yy = (m >> 6) & 63, b = m >> 12;
            As[kk][mm] = g_outh[((size_t)((yy * NB + b) * FEAT) + k0 + kk) * NW + w];
        }
#pragma unroll
        for (int i = 0; i < 4; i++) {
            int idx = tid + i * 256;
            int kk = idx >> 6, nn = idx & 63;
            Bs[kk][nn] = g_wS[(k0 + kk) * CIN + n0 + nn];
        }
        __syncthreads();
#pragma unroll
        for (int k = 0; k < 16; k++) {
            float4 aA = *(const float4*)&As[k][tx * 4];
            float4 aB = *(const float4*)&As[k][64 + tx * 4];
            float4 bv = *(const float4*)&Bs[k][ty * 4];
            float av[2][4] = {{aA.x, aA.y, aA.z, aA.w}, {aB.x, aB.y, aB.z, aB.w}};
            float bb[4] = {bv.x, bv.y, bv.z, bv.w};
#pragma unroll
            for (int h = 0; h < 2; h++)
#pragma unroll
                for (int i = 0; i < 4; i++)
#pragma unroll
                    for (int j = 0; j < 4; j++)
                        acc[h][i][j] = fmaf(av[h][i], bb[j], acc[h][i][j]);
        }
        __syncthreads();
    }
#pragma unroll
    for (int h = 0; h < 2; h++) {
        int m = m0 + h * 64 + tx * 4;
        int w = m & 63, yy = (m >> 6) & 63, b = m >> 12;
#pragma unroll
        for (int j = 0; j < 4; j++) {
            int n = n0 + ty * 4 + j;
            size_t base = ((size_t)(b * CIN + n) * NH + yy) * NW + w;
            float4 xv = *(const float4*)&x[base];
            float bs = b_skip[n];
            float4 ov = make_float4(acc[h][0][j] + xv.x + bs,
                                    acc[h][1][j] + xv.y + bs,
                                    acc[h][2][j] + xv.z + bs,
                                    acc[h][3][j] + xv.w + bs);
            *(float4*)&out[base] = ov;
        }
    }
}

// ---------------- launch ----------------
extern "C" void kernel_launch(void* const* d_in, const int* in_sizes, int n_in,
                              void* d_out, int out_size) {
    const float* x = 0; const float* w_i2s = 0; const float* w_s2s = 0;
    const float* w_skip = 0; const float* b_skp = 0;
    for (int i = 0; i < n_in; i++) {
        switch (in_sizes[i]) {
            case NB * CIN * NH * NW:   x      = (const float*)d_in[i]; break;
            case CGATE * CIN * 3:      w_i2s  = (const float*)d_in[i]; break;
            case CGATE * FEAT * 3:     w_s2s  = (const float*)d_in[i]; break;
            case CIN * FEAT:           w_skip = (const float*)d_in[i]; break;
            case CIN:                  b_skp  = (const float*)d_in[i]; break;
        }
    }
    if (!x || !w_i2s || !w_s2s || !w_skip || !b_skp) {
        x      = (const float*)d_in[0];
        w_i2s  = (const float*)d_in[1];
        w_s2s  = (const float*)d_in[2];
        w_skip = (const float*)d_in[3];
        b_skp  = (const float*)d_in[4];
    }
    float* out = (float*)d_out;

    cudaFuncSetAttribute(recurrence, cudaFuncAttributeMaxDynamicSharedMemorySize, SMEM_BYTES);

    prep_weights<<<1024, 256>>>(w_i2s, w_s2s, w_skip);
    phase1_gemm<<<dim3(512, 12), 256>>>(x);
    recurrence<<<NBLK, 256, SMEM_BYTES>>>();
    phase3_gemm<<<dim3(512, 6), 256>>>(x, b_skp, out);
}